// round 5
// baseline (speedup 1.0000x reference)
#include <cuda_runtime.h>
#include <math.h>
#include <cstdint>

#define NN 100000
#define EE 600000
#define DD 128
#define ETOT (EE + NN)

// ---------------- scratch (static device globals; no allocation) ----------------
__device__ float  g_x0[NN * DD];
__device__ float  g_h [NN * DD];
__device__ float  g_el[NN * 4];
__device__ float  g_er[NN * 4];
__device__ float4 g_T [NN];
__device__ float  g_u [DD];
__device__ float  g_vb[DD];
__device__ float  g_sc[16];
__device__ int    g_rowptr[NN + 1];
__device__ int    g_cnt[NN];
__device__ int    g_csr[ETOT];

// ---------------- f32x2 helpers --------------------------------------------------
__device__ __forceinline__ void fma2(uint64_t& acc, uint64_t a, uint64_t b) {
    asm("fma.rn.f32x2 %0, %1, %2, %0;" : "+l"(acc) : "l"(a), "l"(b));
}
__device__ __forceinline__ uint64_t dup2(float a) {
    uint64_t r;
    asm("mov.b64 %0, {%1, %1};" : "=l"(r) : "f"(a));
    return r;
}
__device__ __forceinline__ float2 unp2(uint64_t v) {
    float2 r;
    asm("mov.b64 {%0, %1}, %2;" : "=f"(r.x), "=f"(r.y) : "l"(v));
    return r;
}
__device__ __forceinline__ uint32_t smem_u32(const void* p) {
    uint32_t a;
    asm("{ .reg .u64 t; cvta.to.shared.u64 t, %1; cvt.u32.u64 %0, t; }" : "=r"(a) : "l"(p));
    return a;
}
__device__ __forceinline__ void lds_v2u64(uint64_t& a, uint64_t& b, uint32_t addr) {
    asm volatile("ld.shared.v2.u64 {%0, %1}, [%2];" : "=l"(a), "=l"(b) : "r"(addr));
}

// ---------------- CSR build ------------------------------------------------------
__global__ void k_hist(const int* __restrict__ dst) {
    int i = blockIdx.x * blockDim.x + threadIdx.x;
    if (i < EE) atomicAdd(&g_cnt[dst[i]], 1);
}
__global__ void k_scan() {
    __shared__ int ss[1024];
    int t = threadIdx.x;
    const int chunk = (NN + 1023) / 1024;
    int beg = t * chunk, end = min(beg + chunk, NN);
    int s = 0;
    for (int i = beg; i < end; i++) s += g_cnt[i] + 1;   // +1 = self loop
    ss[t] = s;
    __syncthreads();
    for (int o = 1; o < 1024; o <<= 1) {
        int v = (t >= o) ? ss[t - o] : 0;
        __syncthreads();
        ss[t] += v;
        __syncthreads();
    }
    int run = (t == 0) ? 0 : ss[t - 1];
    for (int i = beg; i < end; i++) {
        int c = g_cnt[i] + 1;
        g_rowptr[i] = run;
        g_cnt[i] = run;
        run += c;
    }
    if (t == 1023) g_rowptr[NN] = ss[1023];
}
__global__ void k_scatter(const int* __restrict__ src, const int* __restrict__ dst) {
    int i = blockIdx.x * blockDim.x + threadIdx.x;
    if (i < EE) {
        int p = atomicAdd(&g_cnt[dst[i]], 1);
        g_csr[p] = src[i];
    } else if (i < EE + NN) {
        int n = i - EE;
        int p = atomicAdd(&g_cnt[n], 1);
        g_csr[p] = n;
    }
}

// ---------------- layer-0 analytic prep ------------------------------------------
__global__ void k_prep(const float* __restrict__ fcW, const float* __restrict__ linW,
                       const float* __restrict__ linb, const float* __restrict__ al,
                       const float* __restrict__ ar, const float* __restrict__ cb) {
    __shared__ float su[128], sv[128];
    int d = threadIdx.x;
    float uu = 0.f, vv = 0.f;
    for (int k = 0; k < 128; k++) {
        float w = fcW[d * 128 + k];
        uu = fmaf(w, linW[k], uu);
        vv = fmaf(w, linb[k], vv);
    }
    su[d] = uu;
    sv[d] = vv;
    g_u[d] = uu;
    g_vb[d] = vv + cb[d];
    __syncthreads();
    if (d < 16) {
        int type = d >> 2, h = d & 3;
        const float* a = (type < 2) ? al : ar;
        const float* base = (type & 1) ? sv : su;
        float s = 0.f;
        for (int f = 0; f < 32; f++) s = fmaf(base[h * 32 + f], a[h * 32 + f], s);
        g_sc[type * 4 + h] = s;
    }
}

// ---------------- layer-0 aggregation --------------------------------------------
__global__ void __launch_bounds__(256) k_agg0(const float* __restrict__ w) {
    int gw = (blockIdx.x * blockDim.x + threadIdx.x) >> 5;
    int lane = threadIdx.x & 31;
    if (gw >= NN) return;
    int n = gw;
    int beg = g_rowptr[n], end = g_rowptr[n + 1];

    float CL0 = g_sc[0], CL1 = g_sc[1], CL2 = g_sc[2], CL3 = g_sc[3];
    float DL0 = g_sc[4], DL1 = g_sc[5], DL2 = g_sc[6], DL3 = g_sc[7];
    float wn = w[n];
    float er0 = fmaf(wn, g_sc[8],  g_sc[12]);
    float er1 = fmaf(wn, g_sc[9],  g_sc[13]);
    float er2 = fmaf(wn, g_sc[10], g_sc[14]);
    float er3 = fmaf(wn, g_sc[11], g_sc[15]);

    float m0 = -3.4e38f, m1 = m0, m2 = m0, m3 = m0;
    for (int j = beg + lane; j < end; j += 32) {
        float ws = w[g_csr[j]];
        float e0 = fmaf(ws, CL0, DL0) + er0; e0 = e0 >= 0.f ? e0 : 0.2f * e0;
        float e1 = fmaf(ws, CL1, DL1) + er1; e1 = e1 >= 0.f ? e1 : 0.2f * e1;
        float e2 = fmaf(ws, CL2, DL2) + er2; e2 = e2 >= 0.f ? e2 : 0.2f * e2;
        float e3 = fmaf(ws, CL3, DL3) + er3; e3 = e3 >= 0.f ? e3 : 0.2f * e3;
        m0 = fmaxf(m0, e0); m1 = fmaxf(m1, e1);
        m2 = fmaxf(m2, e2); m3 = fmaxf(m3, e3);
    }
#pragma unroll
    for (int o = 16; o > 0; o >>= 1) {
        m0 = fmaxf(m0, __shfl_xor_sync(0xffffffffu, m0, o));
        m1 = fmaxf(m1, __shfl_xor_sync(0xffffffffu, m1, o));
        m2 = fmaxf(m2, __shfl_xor_sync(0xffffffffu, m2, o));
        m3 = fmaxf(m3, __shfl_xor_sync(0xffffffffu, m3, o));
    }

    float S0 = 0.f, S1 = 0.f, S2 = 0.f, S3 = 0.f;
    float T0 = 0.f, T1 = 0.f, T2 = 0.f, T3 = 0.f;
    for (int j = beg + lane; j < end; j += 32) {
        float ws = w[g_csr[j]];
        float e0 = fmaf(ws, CL0, DL0) + er0; e0 = e0 >= 0.f ? e0 : 0.2f * e0;
        float e1 = fmaf(ws, CL1, DL1) + er1; e1 = e1 >= 0.f ? e1 : 0.2f * e1;
        float e2 = fmaf(ws, CL2, DL2) + er2; e2 = e2 >= 0.f ? e2 : 0.2f * e2;
        float e3 = fmaf(ws, CL3, DL3) + er3; e3 = e3 >= 0.f ? e3 : 0.2f * e3;
        float p0 = __expf(e0 - m0), p1 = __expf(e1 - m1);
        float p2 = __expf(e2 - m2), p3 = __expf(e3 - m3);
        S0 += p0; S1 += p1; S2 += p2; S3 += p3;
        T0 = fmaf(p0, ws, T0); T1 = fmaf(p1, ws, T1);
        T2 = fmaf(p2, ws, T2); T3 = fmaf(p3, ws, T3);
    }
#pragma unroll
    for (int o = 16; o > 0; o >>= 1) {
        S0 += __shfl_xor_sync(0xffffffffu, S0, o);
        S1 += __shfl_xor_sync(0xffffffffu, S1, o);
        S2 += __shfl_xor_sync(0xffffffffu, S2, o);
        S3 += __shfl_xor_sync(0xffffffffu, S3, o);
        T0 += __shfl_xor_sync(0xffffffffu, T0, o);
        T1 += __shfl_xor_sync(0xffffffffu, T1, o);
        T2 += __shfl_xor_sync(0xffffffffu, T2, o);
        T3 += __shfl_xor_sync(0xffffffffu, T3, o);
    }
    if (lane == 0)
        g_T[n] = make_float4(T0 / S0, T1 / S1, T2 / S2, T3 / S3);
}

// ---------------- GEMM h = leaky(x) @ W^T, packed f32x2, fused el/er ------------
// 128x128 tile per 256-thread CTA; thread = 8 rows (ty*8..) x 8 cols
// (tx*4..+3 and 64+tx*4..+3). Accumulators: 32 packed f32x2 over col pairs.
#define WS_LD 132
template <int MODE>
__global__ void __launch_bounds__(256) k_gemm(const float* __restrict__ W,
                                              const float* __restrict__ al,
                                              const float* __restrict__ ar) {
    __shared__ float xs[128][33];
    __shared__ float ws[32][WS_LD];
    __shared__ float us[128], vbs[128];
    __shared__ float A4[128][4];
    int tid = threadIdx.x;
    int tx = tid & 15, ty = tid >> 4;
    int row0 = blockIdx.x * 128;

    if (MODE == 0) {
        if (tid < 128) {
            us[tid] = g_u[tid];
            vbs[tid] = g_vb[tid];
            int grow = row0 + tid;
            float4 a = (grow < NN) ? g_T[grow] : make_float4(0.f, 0.f, 0.f, 0.f);
            *(float4*)&A4[tid][0] = a;
        }
        __syncthreads();
    }

    uint64_t acc[8][4];
#pragma unroll
    for (int r = 0; r < 8; r++)
#pragma unroll
        for (int c = 0; c < 4; c++) acc[r][c] = 0ull;

    uint32_t ws_base = smem_u32(&ws[0][0]);

    for (int k0 = 0; k0 < 128; k0 += 32) {
        for (int i = tid; i < 128 * 32; i += 256) {
            int r = i >> 5, k = i & 31;
            int kk = k0 + k;
            float v;
            if (MODE == 0) {
                v = fmaf(A4[r][kk >> 5], us[kk], vbs[kk]);
            } else {
                int grow = row0 + r;
                v = (grow < NN) ? g_x0[grow * 128 + kk] : 0.f;
            }
            v = v >= 0.f ? v : 0.01f * v;
            xs[r][k] = v;
        }
        for (int i = tid; i < 128 * 32; i += 256) {
            int d = i >> 5, k = i & 31;
            ws[k][d] = W[d * 128 + k0 + k];
        }
        __syncthreads();
#pragma unroll
        for (int k = 0; k < 32; k++) {
            uint64_t b0, b1, b2, b3;
            uint32_t ba = ws_base + (k * WS_LD + tx * 4) * 4;
            lds_v2u64(b0, b1, ba);
            lds_v2u64(b2, b3, ba + 64 * 4);
#pragma unroll
            for (int r = 0; r < 8; r++) {
                uint64_t aa = dup2(xs[ty * 8 + r][k]);
                fma2(acc[r][0], aa, b0);
                fma2(acc[r][1], aa, b1);
                fma2(acc[r][2], aa, b2);
                fma2(acc[r][3], aa, b3);
            }
        }
        __syncthreads();
    }

    // epilogue
    int j0 = tx * 4, j1 = 64 + tx * 4;
    int hA = tx >> 3, hB = 2 + (tx >> 3);
    float4 alA = *(const float4*)&al[j0], arA = *(const float4*)&ar[j0];
    float4 alB = *(const float4*)&al[j1], arB = *(const float4*)&ar[j1];
#pragma unroll
    for (int r = 0; r < 8; r++) {
        int row = row0 + ty * 8 + r;
        float2 c0 = unp2(acc[r][0]), c1 = unp2(acc[r][1]);
        float2 c2 = unp2(acc[r][2]), c3 = unp2(acc[r][3]);
        float elA = c0.x * alA.x + c0.y * alA.y + c1.x * alA.z + c1.y * alA.w;
        float erA = c0.x * arA.x + c0.y * arA.y + c1.x * arA.z + c1.y * arA.w;
        float elB = c2.x * alB.x + c2.y * alB.y + c3.x * alB.z + c3.y * alB.w;
        float erB = c2.x * arB.x + c2.y * arB.y + c3.x * arB.z + c3.y * arB.w;
#pragma unroll
        for (int o = 1; o <= 4; o <<= 1) {
            elA += __shfl_xor_sync(0xffffffffu, elA, o);
            erA += __shfl_xor_sync(0xffffffffu, erA, o);
            elB += __shfl_xor_sync(0xffffffffu, elB, o);
            erB += __shfl_xor_sync(0xffffffffu, erB, o);
        }
        if (row < NN) {
            *(float4*)&g_h[row * 128 + j0] = make_float4(c0.x, c0.y, c1.x, c1.y);
            *(float4*)&g_h[row * 128 + j1] = make_float4(c2.x, c2.y, c3.x, c3.y);
            if ((tx & 7) == 0) {
                g_el[row * 4 + hA] = elA;
                g_er[row * 4 + hA] = erA;
                g_el[row * 4 + hB] = elB;
                g_er[row * 4 + hB] = erB;
            }
        }
    }
}

// ---------------- edge softmax + aggregation (layers 1,2) ------------------------
__device__ __forceinline__ float sel4(float4 v, int hh) {
    return (hh & 2) ? ((hh & 1) ? v.w : v.z) : ((hh & 1) ? v.y : v.x);
}

template <int FINAL>
__global__ void __launch_bounds__(256) k_agg(const float* __restrict__ bias,
                                             const float* __restrict__ pW,
                                             const float* __restrict__ pb,
                                             float* __restrict__ out) {
    int gw = (blockIdx.x * blockDim.x + threadIdx.x) >> 5;
    int lane = threadIdx.x & 31;
    if (gw >= NN) return;
    int n = gw;
    int beg = g_rowptr[n], end = g_rowptr[n + 1];
    float4 er4 = *(const float4*)&g_er[n * 4];

    float m0 = -3.4e38f, m1 = m0, m2 = m0, m3 = m0;
    for (int j = beg + lane; j < end; j += 32) {
        int s = g_csr[j];
        float4 el4 = *(const float4*)&g_el[s * 4];
        float e0 = el4.x + er4.x; e0 = e0 >= 0.f ? e0 : 0.2f * e0;
        float e1 = el4.y + er4.y; e1 = e1 >= 0.f ? e1 : 0.2f * e1;
        float e2 = el4.z + er4.z; e2 = e2 >= 0.f ? e2 : 0.2f * e2;
        float e3 = el4.w + er4.w; e3 = e3 >= 0.f ? e3 : 0.2f * e3;
        m0 = fmaxf(m0, e0); m1 = fmaxf(m1, e1);
        m2 = fmaxf(m2, e2); m3 = fmaxf(m3, e3);
    }
#pragma unroll
    for (int o = 16; o > 0; o >>= 1) {
        m0 = fmaxf(m0, __shfl_xor_sync(0xffffffffu, m0, o));
        m1 = fmaxf(m1, __shfl_xor_sync(0xffffffffu, m1, o));
        m2 = fmaxf(m2, __shfl_xor_sync(0xffffffffu, m2, o));
        m3 = fmaxf(m3, __shfl_xor_sync(0xffffffffu, m3, o));
    }

    int hh = lane >> 3;
    float mh = (hh & 2) ? ((hh & 1) ? m3 : m2) : ((hh & 1) ? m1 : m0);
    float erh = sel4(er4, hh);

    float a0 = 0.f, a1 = 0.f, a2 = 0.f, a3 = 0.f, sacc = 0.f;
    for (int j = beg; j < end; j++) {
        int s = g_csr[j];
        float4 el4 = *(const float4*)&g_el[s * 4];
        float e = sel4(el4, hh) + erh;
        e = e >= 0.f ? e : 0.2f * e;
        float p = __expf(e - mh);
        float4 hv = *(const float4*)&g_h[s * 128 + lane * 4];
        a0 = fmaf(p, hv.x, a0); a1 = fmaf(p, hv.y, a1);
        a2 = fmaf(p, hv.z, a2); a3 = fmaf(p, hv.w, a3);
        sacc += p;
    }
    float inv = 1.f / sacc;
    int col = lane * 4;
    float4 bv = *(const float4*)&bias[col];
    float4 o = make_float4(fmaf(a0, inv, bv.x), fmaf(a1, inv, bv.y),
                           fmaf(a2, inv, bv.z), fmaf(a3, inv, bv.w));
    if (FINAL) {
        float4 wv = *(const float4*)&pW[col];
        float s = o.x * wv.x + o.y * wv.y + o.z * wv.z + o.w * wv.w;
#pragma unroll
        for (int of = 16; of > 0; of >>= 1) s += __shfl_xor_sync(0xffffffffu, s, of);
        if (lane == 0) out[n] = s + pb[0];
    } else {
        *(float4*)&g_x0[n * 128 + col] = o;
    }
}

// ---------------- launch --------------------------------------------------------
extern "C" void kernel_launch(void* const* d_in, const int* in_sizes, int n_in,
                              void* d_out, int out_size) {
    const float* weights = (const float*)d_in[0];
    const float* linW    = (const float*)d_in[1];
    const float* linb    = (const float*)d_in[2];
    const float* fcW     = (const float*)d_in[3];
    const float* al      = (const float*)d_in[4];
    const float* ar      = (const float*)d_in[5];
    const float* cb      = (const float*)d_in[6];
    const float* pW      = (const float*)d_in[7];
    const float* pb      = (const float*)d_in[8];
    const int*   src     = (const int*)d_in[9];
    const int*   dst     = (const int*)d_in[10];
    float* out = (float*)d_out;

    void* cnt_addr = nullptr;
    cudaGetSymbolAddress(&cnt_addr, g_cnt);
    cudaMemsetAsync(cnt_addr, 0, NN * sizeof(int));

    k_hist<<<(EE + 255) / 256, 256>>>(dst);
    k_scan<<<1, 1024>>>();
    k_scatter<<<(EE + NN + 255) / 256, 256>>>(src, dst);

    k_prep<<<1, 128>>>(fcW, linW, linb, al, ar, cb);

    const int GB = (NN + 127) / 128;
    const int AB = (NN * 32 + 255) / 256;

    k_agg0<<<AB, 256>>>(weights);
    k_gemm<0><<<GB, 256>>>(fcW + DD * DD, al + DD, ar + DD);
    k_agg<0><<<AB, 256>>>(cb + DD, pW, pb, out);
    k_gemm<1><<<GB, 256>>>(fcW + 2 * DD * DD, al + 2 * DD, ar + 2 * DD);
    k_agg<1><<<AB, 256>>>(cb + 2 * DD, pW, pb, out);
}

// round 6
// speedup vs baseline: 2.0766x; 2.0766x over previous
#include <cuda_runtime.h>
#include <math.h>
#include <cstdint>

#define NN 100000
#define EE 600000
#define DD 128
#define ETOT (EE + NN)
#define SCAN_B ((NN + 1023) / 1024)   // 98

// ---------------- scratch (static device globals; no allocation) ----------------
__device__ float  g_x0[NN * DD];
__device__ float  g_h [NN * DD];
__device__ float  g_el[NN * 4];
__device__ float  g_er[NN * 4];
__device__ float4 g_T [NN];
__device__ float  g_u [DD];
__device__ float  g_vb[DD];
__device__ float  g_sc[16];
__device__ int    g_rowptr[NN + 1];
__device__ int    g_cnt[NN];
__device__ int    g_ps [NN];
__device__ int    g_bsum[SCAN_B];
__device__ int    g_boff[SCAN_B];
__device__ int    g_csr[ETOT];

// ---------------- CSR build ------------------------------------------------------
__global__ void k_hist(const int* __restrict__ dst) {
    int i = blockIdx.x * blockDim.x + threadIdx.x;
    if (i < EE) atomicAdd(&g_cnt[dst[i]], 1);
}

// phase A: per-block inclusive scan of (cnt+1), block sums out
__global__ void __launch_bounds__(1024) k_scanA() {
    __shared__ int wsum[32];
    int tid = threadIdx.x, lane = tid & 31, warp = tid >> 5;
    int i = blockIdx.x * 1024 + tid;
    int c = (i < NN) ? g_cnt[i] + 1 : 0;   // +1 = self loop
    int v = c;
#pragma unroll
    for (int o = 1; o < 32; o <<= 1) {
        int t = __shfl_up_sync(0xffffffffu, v, o);
        if (lane >= o) v += t;
    }
    if (lane == 31) wsum[warp] = v;
    __syncthreads();
    if (warp == 0) {
        int w = wsum[lane];
#pragma unroll
        for (int o = 1; o < 32; o <<= 1) {
            int t = __shfl_up_sync(0xffffffffu, w, o);
            if (lane >= o) w += t;
        }
        wsum[lane] = w;
    }
    __syncthreads();
    int incl = v + (warp > 0 ? wsum[warp - 1] : 0);
    if (i < NN) g_ps[i] = incl;
    if (tid == 1023) g_bsum[blockIdx.x] = incl;
}

// phase B: exclusive scan of block sums (single small block)
__global__ void k_scanB() {
    __shared__ int wsum[4];
    int tid = threadIdx.x, lane = tid & 31, warp = tid >> 5;
    int s = (tid < SCAN_B) ? g_bsum[tid] : 0;
    int v = s;
#pragma unroll
    for (int o = 1; o < 32; o <<= 1) {
        int t = __shfl_up_sync(0xffffffffu, v, o);
        if (lane >= o) v += t;
    }
    if (lane == 31) wsum[warp] = v;
    __syncthreads();
    int base = 0;
    for (int w = 0; w < warp; w++) base += wsum[w];
    int incl = v + base;
    if (tid < SCAN_B) g_boff[tid] = incl - s;
    if (tid == 127) g_rowptr[NN] = incl;
}

// phase C: rowptr = exclusive prefix; cnt = scatter cursor
__global__ void __launch_bounds__(1024) k_scanC() {
    int i = blockIdx.x * 1024 + threadIdx.x;
    if (i < NN) {
        int c = g_cnt[i] + 1;
        int e = g_ps[i] - c + g_boff[blockIdx.x];
        g_rowptr[i] = e;
        g_cnt[i] = e;
    }
}

__global__ void k_scatter(const int* __restrict__ src, const int* __restrict__ dst) {
    int i = blockIdx.x * blockDim.x + threadIdx.x;
    if (i < EE) {
        int p = atomicAdd(&g_cnt[dst[i]], 1);
        g_csr[p] = src[i];
    } else if (i < EE + NN) {
        int n = i - EE;
        int p = atomicAdd(&g_cnt[n], 1);
        g_csr[p] = n;
    }
}

// ---------------- layer-0 analytic prep (1024 threads, 8 lanes/output) ----------
__global__ void __launch_bounds__(1024) k_prep(const float* __restrict__ fcW,
                                               const float* __restrict__ linW,
                                               const float* __restrict__ linb,
                                               const float* __restrict__ al,
                                               const float* __restrict__ ar,
                                               const float* __restrict__ cb) {
    __shared__ float su[128], sv[128];
    int tid = threadIdx.x;
    int d = tid >> 3, s = tid & 7;
    float uu = 0.f, vv = 0.f;
#pragma unroll
    for (int q = 0; q < 4; q++) {
        int k = s * 16 + q * 4;
        float4 w = *(const float4*)&fcW[d * 128 + k];
        float4 lw = *(const float4*)&linW[k];
        float4 lb = *(const float4*)&linb[k];
        uu = fmaf(w.x, lw.x, fmaf(w.y, lw.y, fmaf(w.z, lw.z, fmaf(w.w, lw.w, uu))));
        vv = fmaf(w.x, lb.x, fmaf(w.y, lb.y, fmaf(w.z, lb.z, fmaf(w.w, lb.w, vv))));
    }
#pragma unroll
    for (int o = 1; o <= 4; o <<= 1) {
        uu += __shfl_xor_sync(0xffffffffu, uu, o);
        vv += __shfl_xor_sync(0xffffffffu, vv, o);
    }
    if (s == 0) {
        su[d] = uu;
        sv[d] = vv;
        g_u[d] = uu;
        g_vb[d] = vv + cb[d];
    }
    __syncthreads();
    if (tid < 16) {
        int type = tid >> 2, h = tid & 3;
        const float* a = (type < 2) ? al : ar;
        const float* base = (type & 1) ? sv : su;
        float x = 0.f;
        for (int f = 0; f < 32; f++) x = fmaf(base[h * 32 + f], a[h * 32 + f], x);
        g_sc[type * 4 + h] = x;
    }
}

// ---------------- layer-0 aggregation --------------------------------------------
__global__ void __launch_bounds__(256) k_agg0(const float* __restrict__ w) {
    int gw = (blockIdx.x * blockDim.x + threadIdx.x) >> 5;
    int lane = threadIdx.x & 31;
    if (gw >= NN) return;
    int n = gw;
    int beg = g_rowptr[n], end = g_rowptr[n + 1];

    float CL0 = g_sc[0], CL1 = g_sc[1], CL2 = g_sc[2], CL3 = g_sc[3];
    float DL0 = g_sc[4], DL1 = g_sc[5], DL2 = g_sc[6], DL3 = g_sc[7];
    float wn = w[n];
    float er0 = fmaf(wn, g_sc[8],  g_sc[12]);
    float er1 = fmaf(wn, g_sc[9],  g_sc[13]);
    float er2 = fmaf(wn, g_sc[10], g_sc[14]);
    float er3 = fmaf(wn, g_sc[11], g_sc[15]);

    float m0 = -3.4e38f, m1 = m0, m2 = m0, m3 = m0;
    for (int j = beg + lane; j < end; j += 32) {
        float ws = w[g_csr[j]];
        float e0 = fmaf(ws, CL0, DL0) + er0; e0 = e0 >= 0.f ? e0 : 0.2f * e0;
        float e1 = fmaf(ws, CL1, DL1) + er1; e1 = e1 >= 0.f ? e1 : 0.2f * e1;
        float e2 = fmaf(ws, CL2, DL2) + er2; e2 = e2 >= 0.f ? e2 : 0.2f * e2;
        float e3 = fmaf(ws, CL3, DL3) + er3; e3 = e3 >= 0.f ? e3 : 0.2f * e3;
        m0 = fmaxf(m0, e0); m1 = fmaxf(m1, e1);
        m2 = fmaxf(m2, e2); m3 = fmaxf(m3, e3);
    }
#pragma unroll
    for (int o = 16; o > 0; o >>= 1) {
        m0 = fmaxf(m0, __shfl_xor_sync(0xffffffffu, m0, o));
        m1 = fmaxf(m1, __shfl_xor_sync(0xffffffffu, m1, o));
        m2 = fmaxf(m2, __shfl_xor_sync(0xffffffffu, m2, o));
        m3 = fmaxf(m3, __shfl_xor_sync(0xffffffffu, m3, o));
    }

    float S0 = 0.f, S1 = 0.f, S2 = 0.f, S3 = 0.f;
    float T0 = 0.f, T1 = 0.f, T2 = 0.f, T3 = 0.f;
    for (int j = beg + lane; j < end; j += 32) {
        float ws = w[g_csr[j]];
        float e0 = fmaf(ws, CL0, DL0) + er0; e0 = e0 >= 0.f ? e0 : 0.2f * e0;
        float e1 = fmaf(ws, CL1, DL1) + er1; e1 = e1 >= 0.f ? e1 : 0.2f * e1;
        float e2 = fmaf(ws, CL2, DL2) + er2; e2 = e2 >= 0.f ? e2 : 0.2f * e2;
        float e3 = fmaf(ws, CL3, DL3) + er3; e3 = e3 >= 0.f ? e3 : 0.2f * e3;
        float p0 = __expf(e0 - m0), p1 = __expf(e1 - m1);
        float p2 = __expf(e2 - m2), p3 = __expf(e3 - m3);
        S0 += p0; S1 += p1; S2 += p2; S3 += p3;
        T0 = fmaf(p0, ws, T0); T1 = fmaf(p1, ws, T1);
        T2 = fmaf(p2, ws, T2); T3 = fmaf(p3, ws, T3);
    }
#pragma unroll
    for (int o = 16; o > 0; o >>= 1) {
        S0 += __shfl_xor_sync(0xffffffffu, S0, o);
        S1 += __shfl_xor_sync(0xffffffffu, S1, o);
        S2 += __shfl_xor_sync(0xffffffffu, S2, o);
        S3 += __shfl_xor_sync(0xffffffffu, S3, o);
        T0 += __shfl_xor_sync(0xffffffffu, T0, o);
        T1 += __shfl_xor_sync(0xffffffffu, T1, o);
        T2 += __shfl_xor_sync(0xffffffffu, T2, o);
        T3 += __shfl_xor_sync(0xffffffffu, T3, o);
    }
    if (lane == 0)
        g_T[n] = make_float4(T0 / S0, T1 / S1, T2 / S2, T3 / S3);
}

// ---------------- GEMM h = leaky(x) @ W^T fused with el/er (R4 version) ----------
template <int MODE>
__global__ void __launch_bounds__(256) k_gemm(const float* __restrict__ W,
                                              const float* __restrict__ al,
                                              const float* __restrict__ ar) {
    __shared__ float xs[64][33];
    __shared__ float ws[32][132];
    __shared__ float us[128], vbs[128];
    __shared__ float A4[64][4];
    int tid = threadIdx.x;
    int tx = tid & 31, ty = tid >> 5;
    int row0 = blockIdx.x * 64;

    if (MODE == 0) {
        if (tid < 128) {
            us[tid] = g_u[tid];
            vbs[tid] = g_vb[tid];
        } else if (tid < 192) {
            int r = tid - 128;
            int grow = row0 + r;
            float4 a = (grow < NN) ? g_T[grow] : make_float4(0.f, 0.f, 0.f, 0.f);
            *(float4*)&A4[r][0] = a;
        }
        __syncthreads();
    }

    float acc[8][4];
#pragma unroll
    for (int r = 0; r < 8; r++)
#pragma unroll
        for (int c = 0; c < 4; c++) acc[r][c] = 0.f;

    for (int k0 = 0; k0 < 128; k0 += 32) {
        for (int i = tid; i < 64 * 32; i += 256) {
            int r = i >> 5, k = i & 31;
            int kk = k0 + k;
            float v;
            if (MODE == 0) {
                v = fmaf(A4[r][kk >> 5], us[kk], vbs[kk]);
            } else {
                int grow = row0 + r;
                v = (grow < NN) ? g_x0[grow * 128 + kk] : 0.f;
            }
            v = v >= 0.f ? v : 0.01f * v;
            xs[r][k] = v;
        }
        for (int i = tid; i < 128 * 32; i += 256) {
            int d = i >> 5, k = i & 31;
            ws[k][d] = W[d * 128 + k0 + k];
        }
        __syncthreads();
#pragma unroll
        for (int k = 0; k < 32; k++) {
            float4 b = *(const float4*)&ws[k][tx * 4];
#pragma unroll
            for (int r = 0; r < 8; r++) {
                float a = xs[ty * 8 + r][k];
                acc[r][0] = fmaf(a, b.x, acc[r][0]);
                acc[r][1] = fmaf(a, b.y, acc[r][1]);
                acc[r][2] = fmaf(a, b.z, acc[r][2]);
                acc[r][3] = fmaf(a, b.w, acc[r][3]);
            }
        }
        __syncthreads();
    }

    int col = tx * 4;
    float4 alv = *(const float4*)&al[col];
    float4 arv = *(const float4*)&ar[col];
#pragma unroll
    for (int r = 0; r < 8; r++) {
        int row = row0 + ty * 8 + r;
        if (row < NN) {
            *(float4*)&g_h[row * 128 + col] =
                make_float4(acc[r][0], acc[r][1], acc[r][2], acc[r][3]);
            float pl = acc[r][0] * alv.x + acc[r][1] * alv.y + acc[r][2] * alv.z + acc[r][3] * alv.w;
            float pr = acc[r][0] * arv.x + acc[r][1] * arv.y + acc[r][2] * arv.z + acc[r][3] * arv.w;
#pragma unroll
            for (int o = 4; o > 0; o >>= 1) {
                pl += __shfl_xor_sync(0xffffffffu, pl, o);
                pr += __shfl_xor_sync(0xffffffffu, pr, o);
            }
            if ((tx & 7) == 0) {
                int hh = tx >> 3;
                g_el[row * 4 + hh] = pl;
                g_er[row * 4 + hh] = pr;
            }
        }
    }
}

// ---------------- edge softmax + aggregation (layers 1,2) ------------------------
__device__ __forceinline__ float sel4(float4 v, int hh) {
    return (hh & 2) ? ((hh & 1) ? v.w : v.z) : ((hh & 1) ? v.y : v.x);
}

template <int FINAL>
__global__ void __launch_bounds__(256) k_agg(const float* __restrict__ bias,
                                             const float* __restrict__ pW,
                                             const float* __restrict__ pb,
                                             float* __restrict__ out) {
    int gw = (blockIdx.x * blockDim.x + threadIdx.x) >> 5;
    int lane = threadIdx.x & 31;
    if (gw >= NN) return;
    int n = gw;
    int beg = g_rowptr[n], end = g_rowptr[n + 1];
    float4 er4 = *(const float4*)&g_er[n * 4];

    float m0 = -3.4e38f, m1 = m0, m2 = m0, m3 = m0;
    for (int j = beg + lane; j < end; j += 32) {
        int s = g_csr[j];
        float4 el4 = *(const float4*)&g_el[s * 4];
        float e0 = el4.x + er4.x; e0 = e0 >= 0.f ? e0 : 0.2f * e0;
        float e1 = el4.y + er4.y; e1 = e1 >= 0.f ? e1 : 0.2f * e1;
        float e2 = el4.z + er4.z; e2 = e2 >= 0.f ? e2 : 0.2f * e2;
        float e3 = el4.w + er4.w; e3 = e3 >= 0.f ? e3 : 0.2f * e3;
        m0 = fmaxf(m0, e0); m1 = fmaxf(m1, e1);
        m2 = fmaxf(m2, e2); m3 = fmaxf(m3, e3);
    }
#pragma unroll
    for (int o = 16; o > 0; o >>= 1) {
        m0 = fmaxf(m0, __shfl_xor_sync(0xffffffffu, m0, o));
        m1 = fmaxf(m1, __shfl_xor_sync(0xffffffffu, m1, o));
        m2 = fmaxf(m2, __shfl_xor_sync(0xffffffffu, m2, o));
        m3 = fmaxf(m3, __shfl_xor_sync(0xffffffffu, m3, o));
    }

    int hh = lane >> 3;
    float mh = (hh & 2) ? ((hh & 1) ? m3 : m2) : ((hh & 1) ? m1 : m0);
    float erh = sel4(er4, hh);

    float a0 = 0.f, a1 = 0.f, a2 = 0.f, a3 = 0.f, sacc = 0.f;
    for (int j = beg; j < end; j++) {
        int s = g_csr[j];
        float4 el4 = *(const float4*)&g_el[s * 4];
        float e = sel4(el4, hh) + erh;
        e = e >= 0.f ? e : 0.2f * e;
        float p = __expf(e - mh);
        float4 hv = *(const float4*)&g_h[s * 128 + lane * 4];
        a0 = fmaf(p, hv.x, a0); a1 = fmaf(p, hv.y, a1);
        a2 = fmaf(p, hv.z, a2); a3 = fmaf(p, hv.w, a3);
        sacc += p;
    }
    float inv = 1.f / sacc;
    int col = lane * 4;
    float4 bv = *(const float4*)&bias[col];
    float4 o = make_float4(fmaf(a0, inv, bv.x), fmaf(a1, inv, bv.y),
                           fmaf(a2, inv, bv.z), fmaf(a3, inv, bv.w));
    if (FINAL) {
        float4 wv = *(const float4*)&pW[col];
        float s = o.x * wv.x + o.y * wv.y + o.z * wv.z + o.w * wv.w;
#pragma unroll
        for (int of = 16; of > 0; of >>= 1) s += __shfl_xor_sync(0xffffffffu, s, of);
        if (lane == 0) out[n] = s + pb[0];
    } else {
        *(float4*)&g_x0[n * 128 + col] = o;
    }
}

// ---------------- launch --------------------------------------------------------
extern "C" void kernel_launch(void* const* d_in, const int* in_sizes, int n_in,
                              void* d_out, int out_size) {
    const float* weights = (const float*)d_in[0];
    const float* linW    = (const float*)d_in[1];
    const float* linb    = (const float*)d_in[2];
    const float* fcW     = (const float*)d_in[3];
    const float* al      = (const float*)d_in[4];
    const float* ar      = (const float*)d_in[5];
    const float* cb      = (const float*)d_in[6];
    const float* pW      = (const float*)d_in[7];
    const float* pb      = (const float*)d_in[8];
    const int*   src     = (const int*)d_in[9];
    const int*   dst     = (const int*)d_in[10];
    float* out = (float*)d_out;

    void* cnt_addr = nullptr;
    cudaGetSymbolAddress(&cnt_addr, g_cnt);
    cudaMemsetAsync(cnt_addr, 0, NN * sizeof(int));

    k_hist<<<(EE + 255) / 256, 256>>>(dst);
    k_scanA<<<SCAN_B, 1024>>>();
    k_scanB<<<1, 128>>>();
    k_scanC<<<SCAN_B, 1024>>>();
    k_scatter<<<(EE + NN + 255) / 256, 256>>>(src, dst);

    k_prep<<<1, 1024>>>(fcW, linW, linb, al, ar, cb);

    const int GB = (NN + 63) / 64;
    const int AB = (NN * 32 + 255) / 256;

    k_agg0<<<AB, 256>>>(weights);
    k_gemm<0><<<GB, 256>>>(fcW + DD * DD, al + DD, ar + DD);
    k_agg<0><<<AB, 256>>>(cb + DD, pW, pb, out);
    k_gemm<1><<<GB, 256>>>(fcW + 2 * DD * DD, al + 2 * DD, ar + 2 * DD);
    k_agg<1><<<AB, 256>>>(cb + 2 * DD, pW, pb, out);
}

// round 7
// speedup vs baseline: 2.1331x; 1.0272x over previous
#include <cuda_runtime.h>
#include <math.h>
#include <cstdint>

#define NN 100000
#define EE 600000
#define DD 128
#define ETOT (EE + NN)
#define SCAN_B ((NN + 1023) / 1024)   // 98

// ---------------- scratch (static device globals; no allocation) ----------------
__device__ float    g_x0[NN * DD];
__device__ float    g_h [NN * DD];
__device__ float    g_el[NN * 4];
__device__ float    g_er[NN * 4];
__device__ float4   g_T [NN];
__device__ float    g_u [DD];
__device__ float    g_vb[DD];
__device__ float    g_sc[16];
__device__ unsigned g_elmax[8];      // ordered-uint float max: [layer(0/1)][head]
__device__ unsigned g_wmm[2];        // ordered-uint: [0]=max(w), [1]=min(w)
__device__ int      g_rowptr[NN + 1];
__device__ int      g_cnt[NN];
__device__ int      g_ps [NN];
__device__ int      g_bsum[SCAN_B];
__device__ int      g_boff[SCAN_B];
__device__ int      g_csr[ETOT];

// ordered-uint <-> float (monotone map so unsigned atomicMax/Min works)
__device__ __forceinline__ unsigned ford(float f) {
    unsigned u = __float_as_uint(f);
    return (u & 0x80000000u) ? ~u : (u | 0x80000000u);
}
__device__ __forceinline__ float funord(unsigned o) {
    return __uint_as_float((o & 0x80000000u) ? (o ^ 0x80000000u) : ~o);
}

// ---------------- CSR build ------------------------------------------------------
__global__ void k_hist(const int* __restrict__ dst) {
    int i = blockIdx.x * blockDim.x + threadIdx.x;
    if (i < EE) atomicAdd(&g_cnt[dst[i]], 1);
}

__global__ void __launch_bounds__(1024) k_scanA() {
    __shared__ int wsum[32];
    int tid = threadIdx.x, lane = tid & 31, warp = tid >> 5;
    int i = blockIdx.x * 1024 + tid;
    int c = (i < NN) ? g_cnt[i] + 1 : 0;   // +1 = self loop
    int v = c;
#pragma unroll
    for (int o = 1; o < 32; o <<= 1) {
        int t = __shfl_up_sync(0xffffffffu, v, o);
        if (lane >= o) v += t;
    }
    if (lane == 31) wsum[warp] = v;
    __syncthreads();
    if (warp == 0) {
        int w = wsum[lane];
#pragma unroll
        for (int o = 1; o < 32; o <<= 1) {
            int t = __shfl_up_sync(0xffffffffu, w, o);
            if (lane >= o) w += t;
        }
        wsum[lane] = w;
    }
    __syncthreads();
    int incl = v + (warp > 0 ? wsum[warp - 1] : 0);
    if (i < NN) g_ps[i] = incl;
    if (tid == 1023) g_bsum[blockIdx.x] = incl;
}

__global__ void k_scanB() {
    __shared__ int wsum[4];
    int tid = threadIdx.x, lane = tid & 31, warp = tid >> 5;
    int s = (tid < SCAN_B) ? g_bsum[tid] : 0;
    int v = s;
#pragma unroll
    for (int o = 1; o < 32; o <<= 1) {
        int t = __shfl_up_sync(0xffffffffu, v, o);
        if (lane >= o) v += t;
    }
    if (lane == 31) wsum[warp] = v;
    __syncthreads();
    int base = 0;
    for (int w = 0; w < warp; w++) base += wsum[w];
    int incl = v + base;
    if (tid < SCAN_B) g_boff[tid] = incl - s;
    if (tid == 127) g_rowptr[NN] = incl;
}

__global__ void __launch_bounds__(1024) k_scanC() {
    int i = blockIdx.x * 1024 + threadIdx.x;
    if (i < NN) {
        int c = g_cnt[i] + 1;
        int e = g_ps[i] - c + g_boff[blockIdx.x];
        g_rowptr[i] = e;
        g_cnt[i] = e;
    }
}

__global__ void k_scatter(const int* __restrict__ src, const int* __restrict__ dst) {
    int i = blockIdx.x * blockDim.x + threadIdx.x;
    if (i < EE) {
        int p = atomicAdd(&g_cnt[dst[i]], 1);
        g_csr[p] = src[i];
    } else if (i < EE + NN) {
        int n = i - EE;
        int p = atomicAdd(&g_cnt[n], 1);
        g_csr[p] = n;
    }
}

// ---------------- global weight min/max ------------------------------------------
__global__ void __launch_bounds__(256) k_wmm(const float* __restrict__ w) {
    int i = blockIdx.x * blockDim.x + threadIdx.x;
    float v = (i < NN) ? w[i] : w[0];
    float mx = v, mn = v;
#pragma unroll
    for (int o = 16; o > 0; o >>= 1) {
        mx = fmaxf(mx, __shfl_xor_sync(0xffffffffu, mx, o));
        mn = fminf(mn, __shfl_xor_sync(0xffffffffu, mn, o));
    }
    if ((threadIdx.x & 31) == 0) {
        atomicMax(&g_wmm[0], ford(mx));
        atomicMin(&g_wmm[1], ford(mn));
    }
}

// ---------------- layer-0 analytic prep ------------------------------------------
__global__ void __launch_bounds__(1024) k_prep(const float* __restrict__ fcW,
                                               const float* __restrict__ linW,
                                               const float* __restrict__ linb,
                                               const float* __restrict__ al,
                                               const float* __restrict__ ar,
                                               const float* __restrict__ cb) {
    __shared__ float su[128], sv[128];
    int tid = threadIdx.x;
    int d = tid >> 3, s = tid & 7;
    float uu = 0.f, vv = 0.f;
#pragma unroll
    for (int q = 0; q < 4; q++) {
        int k = s * 16 + q * 4;
        float4 w = *(const float4*)&fcW[d * 128 + k];
        float4 lw = *(const float4*)&linW[k];
        float4 lb = *(const float4*)&linb[k];
        uu = fmaf(w.x, lw.x, fmaf(w.y, lw.y, fmaf(w.z, lw.z, fmaf(w.w, lw.w, uu))));
        vv = fmaf(w.x, lb.x, fmaf(w.y, lb.y, fmaf(w.z, lb.z, fmaf(w.w, lb.w, vv))));
    }
#pragma unroll
    for (int o = 1; o <= 4; o <<= 1) {
        uu += __shfl_xor_sync(0xffffffffu, uu, o);
        vv += __shfl_xor_sync(0xffffffffu, vv, o);
    }
    if (s == 0) {
        su[d] = uu;
        sv[d] = vv;
        g_u[d] = uu;
        g_vb[d] = vv + cb[d];
    }
    __syncthreads();
    if (tid < 16) {
        int type = tid >> 2, h = tid & 3;
        const float* a = (type < 2) ? al : ar;
        const float* base = (type & 1) ? sv : su;
        float x = 0.f;
        for (int f = 0; f < 32; f++) x = fmaf(base[h * 32 + f], a[h * 32 + f], x);
        g_sc[type * 4 + h] = x;
    }
}

// ---------------- layer-0 aggregation (single pass, analytic max bound) ----------
__global__ void __launch_bounds__(256) k_agg0(const float* __restrict__ w) {
    int gw = (blockIdx.x * blockDim.x + threadIdx.x) >> 5;
    int lane = threadIdx.x & 31;
    if (gw >= NN) return;
    int n = gw;
    int beg = g_rowptr[n], end = g_rowptr[n + 1];

    float CL0 = g_sc[0], CL1 = g_sc[1], CL2 = g_sc[2], CL3 = g_sc[3];
    float DL0 = g_sc[4], DL1 = g_sc[5], DL2 = g_sc[6], DL3 = g_sc[7];
    float wn = w[n];
    float er0 = fmaf(wn, g_sc[8],  g_sc[12]);
    float er1 = fmaf(wn, g_sc[9],  g_sc[13]);
    float er2 = fmaf(wn, g_sc[10], g_sc[14]);
    float er3 = fmaf(wn, g_sc[11], g_sc[15]);

    float wmax = funord(g_wmm[0]), wmin = funord(g_wmm[1]);
    float m0 = fmaf(CL0 >= 0.f ? wmax : wmin, CL0, DL0) + er0; m0 = m0 >= 0.f ? m0 : 0.2f * m0;
    float m1 = fmaf(CL1 >= 0.f ? wmax : wmin, CL1, DL1) + er1; m1 = m1 >= 0.f ? m1 : 0.2f * m1;
    float m2 = fmaf(CL2 >= 0.f ? wmax : wmin, CL2, DL2) + er2; m2 = m2 >= 0.f ? m2 : 0.2f * m2;
    float m3 = fmaf(CL3 >= 0.f ? wmax : wmin, CL3, DL3) + er3; m3 = m3 >= 0.f ? m3 : 0.2f * m3;

    float S0 = 0.f, S1 = 0.f, S2 = 0.f, S3 = 0.f;
    float T0 = 0.f, T1 = 0.f, T2 = 0.f, T3 = 0.f;
    for (int j = beg + lane; j < end; j += 32) {
        float ws = w[g_csr[j]];
        float e0 = fmaf(ws, CL0, DL0) + er0; e0 = e0 >= 0.f ? e0 : 0.2f * e0;
        float e1 = fmaf(ws, CL1, DL1) + er1; e1 = e1 >= 0.f ? e1 : 0.2f * e1;
        float e2 = fmaf(ws, CL2, DL2) + er2; e2 = e2 >= 0.f ? e2 : 0.2f * e2;
        float e3 = fmaf(ws, CL3, DL3) + er3; e3 = e3 >= 0.f ? e3 : 0.2f * e3;
        float p0 = __expf(e0 - m0), p1 = __expf(e1 - m1);
        float p2 = __expf(e2 - m2), p3 = __expf(e3 - m3);
        S0 += p0; S1 += p1; S2 += p2; S3 += p3;
        T0 = fmaf(p0, ws, T0); T1 = fmaf(p1, ws, T1);
        T2 = fmaf(p2, ws, T2); T3 = fmaf(p3, ws, T3);
    }
#pragma unroll
    for (int o = 16; o > 0; o >>= 1) {
        S0 += __shfl_xor_sync(0xffffffffu, S0, o);
        S1 += __shfl_xor_sync(0xffffffffu, S1, o);
        S2 += __shfl_xor_sync(0xffffffffu, S2, o);
        S3 += __shfl_xor_sync(0xffffffffu, S3, o);
        T0 += __shfl_xor_sync(0xffffffffu, T0, o);
        T1 += __shfl_xor_sync(0xffffffffu, T1, o);
        T2 += __shfl_xor_sync(0xffffffffu, T2, o);
        T3 += __shfl_xor_sync(0xffffffffu, T3, o);
    }
    if (lane == 0)
        g_T[n] = make_float4(T0 / S0, T1 / S1, T2 / S2, T3 / S3);
}

// ---------------- GEMM h = leaky(x) @ W^T fused with el/er + el max -------------
template <int MODE>
__global__ void __launch_bounds__(256) k_gemm(const float* __restrict__ W,
                                              const float* __restrict__ al,
                                              const float* __restrict__ ar) {
    __shared__ float xs[64][33];
    __shared__ float ws[32][132];
    __shared__ float us[128], vbs[128];
    __shared__ float A4[64][4];
    __shared__ unsigned selmax[4];
    int tid = threadIdx.x;
    int tx = tid & 31, ty = tid >> 5;
    int row0 = blockIdx.x * 64;

    if (tid < 4) selmax[tid] = 0u;
    if (MODE == 0) {
        if (tid < 128) {
            us[tid] = g_u[tid];
            vbs[tid] = g_vb[tid];
        } else if (tid < 192) {
            int r = tid - 128;
            int grow = row0 + r;
            float4 a = (grow < NN) ? g_T[grow] : make_float4(0.f, 0.f, 0.f, 0.f);
            *(float4*)&A4[r][0] = a;
        }
    }
    __syncthreads();

    float acc[8][4];
#pragma unroll
    for (int r = 0; r < 8; r++)
#pragma unroll
        for (int c = 0; c < 4; c++) acc[r][c] = 0.f;

    for (int k0 = 0; k0 < 128; k0 += 32) {
        for (int i = tid; i < 64 * 32; i += 256) {
            int r = i >> 5, k = i & 31;
            int kk = k0 + k;
            float v;
            if (MODE == 0) {
                v = fmaf(A4[r][kk >> 5], us[kk], vbs[kk]);
            } else {
                int grow = row0 + r;
                v = (grow < NN) ? g_x0[grow * 128 + kk] : 0.f;
            }
            v = v >= 0.f ? v : 0.01f * v;
            xs[r][k] = v;
        }
        for (int i = tid; i < 128 * 32; i += 256) {
            int d = i >> 5, k = i & 31;
            ws[k][d] = W[d * 128 + k0 + k];
        }
        __syncthreads();
#pragma unroll
        for (int k = 0; k < 32; k++) {
            float4 b = *(const float4*)&ws[k][tx * 4];
#pragma unroll
            for (int r = 0; r < 8; r++) {
                float a = xs[ty * 8 + r][k];
                acc[r][0] = fmaf(a, b.x, acc[r][0]);
                acc[r][1] = fmaf(a, b.y, acc[r][1]);
                acc[r][2] = fmaf(a, b.z, acc[r][2]);
                acc[r][3] = fmaf(a, b.w, acc[r][3]);
            }
        }
        __syncthreads();
    }

    int col = tx * 4;
    float4 alv = *(const float4*)&al[col];
    float4 arv = *(const float4*)&ar[col];
    unsigned lmax = 0u;
#pragma unroll
    for (int r = 0; r < 8; r++) {
        int row = row0 + ty * 8 + r;
        float pl = acc[r][0] * alv.x + acc[r][1] * alv.y + acc[r][2] * alv.z + acc[r][3] * alv.w;
        float pr = acc[r][0] * arv.x + acc[r][1] * arv.y + acc[r][2] * arv.z + acc[r][3] * arv.w;
#pragma unroll
        for (int o = 4; o > 0; o >>= 1) {
            pl += __shfl_xor_sync(0xffffffffu, pl, o);
            pr += __shfl_xor_sync(0xffffffffu, pr, o);
        }
        if (row < NN) {
            *(float4*)&g_h[row * 128 + col] =
                make_float4(acc[r][0], acc[r][1], acc[r][2], acc[r][3]);
            if ((tx & 7) == 0) {
                int hh = tx >> 3;
                g_el[row * 4 + hh] = pl;
                g_er[row * 4 + hh] = pr;
                unsigned f = ford(pl);
                if (f > lmax) lmax = f;
            }
        }
    }
    if ((tx & 7) == 0 && lmax) atomicMax(&selmax[tx >> 3], lmax);
    __syncthreads();
    if (tid < 4 && selmax[tid]) atomicMax(&g_elmax[MODE * 4 + tid], selmax[tid]);
}

// ---------------- edge softmax + aggregation (single pass, bound max) -----------
__device__ __forceinline__ float sel4(float4 v, int hh) {
    return (hh & 2) ? ((hh & 1) ? v.w : v.z) : ((hh & 1) ? v.y : v.x);
}

template <int FINAL>
__global__ void __launch_bounds__(256) k_agg(const float* __restrict__ bias,
                                             const float* __restrict__ pW,
                                             const float* __restrict__ pb,
                                             float* __restrict__ out) {
    int gw = (blockIdx.x * blockDim.x + threadIdx.x) >> 5;
    int lane = threadIdx.x & 31;
    if (gw >= NN) return;
    int n = gw;
    int beg = g_rowptr[n], end = g_rowptr[n + 1];
    float4 er4 = *(const float4*)&g_er[n * 4];

    int hh = lane >> 3;
    float erh = sel4(er4, hh);
    float mh = funord(g_elmax[FINAL * 4 + hh]) + erh;   // >= el[s]+er[n] for all s
    mh = mh >= 0.f ? mh : 0.2f * mh;                    // leaky monotone => bound on e

    float a0 = 0.f, a1 = 0.f, a2 = 0.f, a3 = 0.f, sacc = 0.f;
    for (int j = beg; j < end; j++) {
        int s = g_csr[j];
        float4 el4 = *(const float4*)&g_el[s * 4];
        float e = sel4(el4, hh) + erh;
        e = e >= 0.f ? e : 0.2f * e;
        float p = __expf(e - mh);
        float4 hv = *(const float4*)&g_h[s * 128 + lane * 4];
        a0 = fmaf(p, hv.x, a0); a1 = fmaf(p, hv.y, a1);
        a2 = fmaf(p, hv.z, a2); a3 = fmaf(p, hv.w, a3);
        sacc += p;
    }
    float inv = 1.f / sacc;
    int col = lane * 4;
    float4 bv = *(const float4*)&bias[col];
    float4 o = make_float4(fmaf(a0, inv, bv.x), fmaf(a1, inv, bv.y),
                           fmaf(a2, inv, bv.z), fmaf(a3, inv, bv.w));
    if (FINAL) {
        float4 wv = *(const float4*)&pW[col];
        float s = o.x * wv.x + o.y * wv.y + o.z * wv.z + o.w * wv.w;
#pragma unroll
        for (int of = 16; of > 0; of >>= 1) s += __shfl_xor_sync(0xffffffffu, s, of);
        if (lane == 0) out[n] = s + pb[0];
    } else {
        *(float4*)&g_x0[n * 128 + col] = o;
    }
}

// ---------------- launch --------------------------------------------------------
extern "C" void kernel_launch(void* const* d_in, const int* in_sizes, int n_in,
                              void* d_out, int out_size) {
    const float* weights = (const float*)d_in[0];
    const float* linW    = (const float*)d_in[1];
    const float* linb    = (const float*)d_in[2];
    const float* fcW     = (const float*)d_in[3];
    const float* al      = (const float*)d_in[4];
    const float* ar      = (const float*)d_in[5];
    const float* cb      = (const float*)d_in[6];
    const float* pW      = (const float*)d_in[7];
    const float* pb      = (const float*)d_in[8];
    const int*   src     = (const int*)d_in[9];
    const int*   dst     = (const int*)d_in[10];
    float* out = (float*)d_out;

    void* p = nullptr;
    cudaGetSymbolAddress(&p, g_cnt);
    cudaMemsetAsync(p, 0, NN * sizeof(int));
    cudaGetSymbolAddress(&p, g_elmax);
    cudaMemsetAsync(p, 0, 8 * sizeof(unsigned));
    cudaGetSymbolAddress(&p, g_wmm);
    cudaMemsetAsync(p, 0x00, sizeof(unsigned));                       // wmax ordered init
    cudaMemsetAsync((char*)p + sizeof(unsigned), 0xFF, sizeof(unsigned));  // wmin ordered init

    k_hist<<<(EE + 255) / 256, 256>>>(dst);
    k_scanA<<<SCAN_B, 1024>>>();
    k_scanB<<<1, 128>>>();
    k_scanC<<<SCAN_B, 1024>>>();
    k_scatter<<<(EE + NN + 255) / 256, 256>>>(src, dst);

    k_wmm<<<(NN + 255) / 256, 256>>>(weights);
    k_prep<<<1, 1024>>>(fcW, linW, linb, al, ar, cb);

    const int GB = (NN + 63) / 64;
    const int AB = (NN * 32 + 255) / 256;

    k_agg0<<<AB, 256>>>(weights);
    k_gemm<0><<<GB, 256>>>(fcW + DD * DD, al + DD, ar + DD);
    k_agg<0><<<AB, 256>>>(cb + DD, pW, pb, out);
    k_gemm<1><<<GB, 256>>>(fcW + 2 * DD * DD, al + 2 * DD, ar + 2 * DD);
    k_agg<1><<<AB, 256>>>(cb + 2 * DD, pW, pb, out);
}